// round 1
// baseline (speedup 1.0000x reference)
#include <cuda_runtime.h>

#define NCLS   10
#define NB     32
#define NAT    512
#define NATOMS 16384          // NB * NAT
#define DIN    272
#define HID    64
#define NOUT   128
#define L0OUT  256
#define IN0    32
#define ATILE  64
#define NTHREADS 256
#define TILES_PER_CLASS (NATOMS / ATILE)   // 256

// scratch (static device globals — no runtime allocation)
__device__ int g_cnt[16];
__device__ int g_list[NCLS * NATOMS];

// ---------------------------------------------------------------------------
// Kernel 1: zero the output accumulator and the per-class counters
// ---------------------------------------------------------------------------
__global__ void prep_kernel(float* __restrict__ out, int n) {
    int i = blockIdx.x * blockDim.x + threadIdx.x;
    if (i < n) out[i] = 0.0f;
    if (i < 16) g_cnt[i] = 0;
}

// ---------------------------------------------------------------------------
// Kernel 2: counting-sort atoms into per-class lists (class 10 is dropped:
// mapping in [0,11) but only T=10 classes contribute)
// ---------------------------------------------------------------------------
__global__ void compact_kernel(const int* __restrict__ mapping) {
    int n = blockIdx.x * blockDim.x + threadIdx.x;
    if (n >= NATOMS) return;
    int m = mapping[n];
    if ((unsigned)m < NCLS) {
        int pos = atomicAdd(&g_cnt[m], 1);
        g_list[m * NATOMS + pos] = n;
    }
}

__device__ __forceinline__ float silu_f(float x) {
    return x * (1.0f / (1.0f + __expf(-x)));
}

// ---------------------------------------------------------------------------
// Kernel 3: fused 3-stage scalar MLP per (class, atom-tile), scatter-add out.
//   s1 = silu( (x[:, :32] @ W0_0[cls][:, :64]) / sqrt(32) )
//   s2 = silu( (s1        @ W1_0[cls][:, :64]) / 8 )
//   y  =       (s2        @ Wout[cls])          / 8
//   out[b, cls*128 + o] += y
// ---------------------------------------------------------------------------
__global__ __launch_bounds__(NTHREADS) void mlp_kernel(
    const float* __restrict__ af,   // (NATOMS, 272)
    const float* __restrict__ W0,   // (T, 32, 256)
    const float* __restrict__ W1,   // (T, 64, 256)
    const float* __restrict__ Wo,   // (T, 64, 128)
    float* __restrict__ out)        // (NB, T*128)
{
    extern __shared__ float sm[];
    float* Wa = sm;                    // [32][64]  = 2048
    float* Wb = Wa + IN0 * HID;        // [64][64]  = 4096
    float* Wc = Wb + HID * HID;        // [64][128] = 8192
    float* xs = Wc + HID * NOUT;       // [64][33]  (padded)
    float* s1 = xs + ATILE * 33;       // [64][65]  (padded)
    float* s2 = s1 + ATILE * 65;       // [64][65]
    int*  aid = (int*)(s2 + ATILE * 65);  // [64]

    const int cls  = blockIdx.x / TILES_PER_CLASS;
    const int tile = blockIdx.x % TILES_PER_CLASS;
    const int cnt  = g_cnt[cls];
    const int base = tile * ATILE;
    if (base >= cnt) return;

    const int t = threadIdx.x;

    if (t < ATILE) {
        int i = base + t;
        aid[t] = (i < cnt) ? g_list[cls * NATOMS + i] : -1;
    }
    __syncthreads();

    // --- stage weights into SMEM (only the live 64 columns of W0_0/W1_0) ---
    const float* w0p = W0 + (size_t)cls * IN0 * L0OUT;
    for (int i = t; i < IN0 * HID; i += NTHREADS)
        Wa[i] = w0p[(i >> 6) * L0OUT + (i & 63)];
    const float* w1p = W1 + (size_t)cls * HID * L0OUT;
    for (int i = t; i < HID * HID; i += NTHREADS)
        Wb[i] = w1p[(i >> 6) * L0OUT + (i & 63)];
    const float* wop = Wo + (size_t)cls * HID * NOUT;
    for (int i = t; i < HID * NOUT; i += NTHREADS)
        Wc[i] = wop[i];
    // --- gather atom scalar features (first 32 of 272) ---
    for (int i = t; i < ATILE * IN0; i += NTHREADS) {
        int a = i >> 5, m = i & 31;
        int id = aid[a];
        xs[a * 33 + m] = (id >= 0) ? af[(size_t)id * DIN + m] : 0.0f;
    }
    __syncthreads();

    const float RS32 = 0.17677669529663687f;  // 1/sqrt(32)

    // --- stage 1: [64 x 32] @ [32 x 64], 4x4 micro-tile per thread ---
    {
        const int a0 = (t >> 4) << 2;
        const int o0 = (t & 15) << 2;
        float acc[4][4] = {};
        #pragma unroll 8
        for (int k = 0; k < IN0; k++) {
            float xv[4], wv[4];
            #pragma unroll
            for (int i = 0; i < 4; i++) xv[i] = xs[(a0 + i) * 33 + k];
            #pragma unroll
            for (int j = 0; j < 4; j++) wv[j] = Wa[k * HID + o0 + j];
            #pragma unroll
            for (int i = 0; i < 4; i++)
                #pragma unroll
                for (int j = 0; j < 4; j++)
                    acc[i][j] += xv[i] * wv[j];
        }
        #pragma unroll
        for (int i = 0; i < 4; i++)
            #pragma unroll
            for (int j = 0; j < 4; j++)
                s1[(a0 + i) * 65 + o0 + j] = silu_f(acc[i][j] * RS32);
    }
    __syncthreads();

    // --- stage 2: [64 x 64] @ [64 x 64] ---
    {
        const int a0 = (t >> 4) << 2;
        const int o0 = (t & 15) << 2;
        float acc[4][4] = {};
        #pragma unroll 8
        for (int k = 0; k < HID; k++) {
            float xv[4], wv[4];
            #pragma unroll
            for (int i = 0; i < 4; i++) xv[i] = s1[(a0 + i) * 65 + k];
            #pragma unroll
            for (int j = 0; j < 4; j++) wv[j] = Wb[k * HID + o0 + j];
            #pragma unroll
            for (int i = 0; i < 4; i++)
                #pragma unroll
                for (int j = 0; j < 4; j++)
                    acc[i][j] += xv[i] * wv[j];
        }
        #pragma unroll
        for (int i = 0; i < 4; i++)
            #pragma unroll
            for (int j = 0; j < 4; j++)
                s2[(a0 + i) * 65 + o0 + j] = silu_f(acc[i][j] * 0.125f);
    }
    __syncthreads();

    // --- stage 3: [64 x 64] @ [64 x 128], 8x4 micro-tile, scatter-add ---
    {
        const int a0 = (t >> 5) << 3;   // 8 atom-groups of 8
        const int o0 = (t & 31) << 2;   // 32 out-groups of 4
        float acc[8][4] = {};
        #pragma unroll 8
        for (int k = 0; k < HID; k++) {
            float xv[8], wv[4];
            #pragma unroll
            for (int i = 0; i < 8; i++) xv[i] = s2[(a0 + i) * 65 + k];
            #pragma unroll
            for (int j = 0; j < 4; j++) wv[j] = Wc[k * NOUT + o0 + j];
            #pragma unroll
            for (int i = 0; i < 8; i++)
                #pragma unroll
                for (int j = 0; j < 4; j++)
                    acc[i][j] += xv[i] * wv[j];
        }
        #pragma unroll
        for (int i = 0; i < 8; i++) {
            int id = aid[a0 + i];
            if (id >= 0) {
                int b = id >> 9;  // id / NAT
                float* op = out + (size_t)b * (NCLS * NOUT) + cls * NOUT + o0;
                #pragma unroll
                for (int j = 0; j < 4; j++)
                    atomicAdd(op + j, acc[i][j] * 0.125f);
            }
        }
    }
}

// ---------------------------------------------------------------------------
extern "C" void kernel_launch(void* const* d_in, const int* in_sizes, int n_in,
                              void* d_out, int out_size) {
    const float* af      = (const float*)d_in[0];   // atom_features
    const float* W0      = (const float*)d_in[1];   // W0_0
    const float* W1      = (const float*)d_in[5];   // W1_0
    const float* Wo      = (const float*)d_in[9];   // Wout
    const int*   mapping = (const int*)  d_in[10];  // mlp_mapping
    float* out = (float*)d_out;

    const int smem_bytes = (IN0 * HID + HID * HID + HID * NOUT +
                            ATILE * 33 + 2 * ATILE * 65) * 4 + ATILE * 4;
    cudaFuncSetAttribute(mlp_kernel,
                         cudaFuncAttributeMaxDynamicSharedMemorySize,
                         smem_bytes);

    const int n_out_elems = NB * NCLS * NOUT;  // 40960
    prep_kernel<<<(n_out_elems + 255) / 256, 256>>>(out, n_out_elems);
    compact_kernel<<<NATOMS / 256, 256>>>(mapping);
    mlp_kernel<<<NCLS * TILES_PER_CLASS, NTHREADS, smem_bytes>>>(
        af, W0, W1, Wo, out);
}

// round 2
// speedup vs baseline: 1.0662x; 1.0662x over previous
#include <cuda_runtime.h>

#define NCLS   10
#define NB     32
#define NAT    512
#define NATOMS 16384
#define DIN    272
#define HID    64
#define NOUT   128
#define L0OUT  256
#define IN0    32
#define ATILE  64
#define MLP_THREADS 64
#define TILES_PER_CLASS 256        // worst-case tiles per class
#define PAD1   68                  // s1 row pad (floats), 16B-aligned rows

// static device scratch (no runtime allocation)
__device__ int   g_cnt[16];                 // zero at module load; reset by out_kernel
__device__ int   g_list[NCLS * NATOMS];
__device__ float g_acc[NB * NCLS * HID];    // 20480 floats: sum of s2 per (b, cls)

__device__ __forceinline__ float silu_f(float x) {
    return x * (1.0f / (1.0f + __expf(-x)));
}

// ---------------------------------------------------------------------------
// Kernel 1: zero g_acc + counting-sort atoms by class (class 10 dropped).
// g_cnt is guaranteed zero on entry (module init / reset by previous call's
// out_kernel), so zeroing and counting are independent here.
// ---------------------------------------------------------------------------
__global__ void prep_compact_kernel(const int* __restrict__ mapping) {
    int n = blockIdx.x * blockDim.x + threadIdx.x;     // 0..16383
    g_acc[n] = 0.0f;
    if (n < NB * NCLS * HID - NATOMS)                  // remaining 4096
        g_acc[n + NATOMS] = 0.0f;
    int m = mapping[n];
    if ((unsigned)m < NCLS) {
        int pos = atomicAdd(&g_cnt[m], 1);
        g_list[m * NATOMS + pos] = n;
    }
}

// ---------------------------------------------------------------------------
// Kernel 2: fused 2-stage scalar MLP per (class, 64-atom tile).
//   s1 = silu((x32 @ W0_0[:, :64]) / sqrt(32))
//   s2 = silu((s1  @ W1_0[:, :64]) / 8)
//   g_acc[b][cls][:] += s2           (REDG scatter-add, linear stage-3 deferred)
// 64 threads, 8x8 register micro-tiles, [k][atom]-transposed smem for LDS.128.
// ---------------------------------------------------------------------------
__global__ __launch_bounds__(MLP_THREADS) void mlp_kernel(
    const float* __restrict__ af,   // (16384, 272)
    const float* __restrict__ W0,   // (T, 32, 256)
    const float* __restrict__ W1)   // (T, 64, 256)
{
    __shared__ float Wa[IN0 * HID];     // [k][o]  2048 f
    __shared__ float Wb[HID * HID];     // [k][o]  4096 f
    __shared__ float xs[IN0 * ATILE];   // [k][a]  2048 f
    __shared__ float s1[HID * PAD1];    // [k][a]  4352 f
    __shared__ int   aid[ATILE];

    const int cls  = blockIdx.x / TILES_PER_CLASS;
    const int tile = blockIdx.x % TILES_PER_CLASS;
    const int cnt  = g_cnt[cls];
    const int base = tile * ATILE;
    if (base >= cnt) return;

    const int t = threadIdx.x;

    // atom ids for this tile
    {
        int i = base + t;
        aid[t] = (i < cnt) ? g_list[cls * NATOMS + i] : -1;
    }

    // --- stage weights into SMEM, [k][o] with o<64 live columns ---
    const float4* w0p = (const float4*)(W0 + (size_t)cls * IN0 * L0OUT);
    #pragma unroll
    for (int r = 0; r < 8; r++) {                  // 512 float4s
        int idx = r * MLP_THREADS + t;
        int k = idx >> 4, c = idx & 15;
        ((float4*)Wa)[k * 16 + c] = w0p[k * 64 + c];
    }
    const float4* w1p = (const float4*)(W1 + (size_t)cls * HID * L0OUT);
    #pragma unroll
    for (int r = 0; r < 16; r++) {                 // 1024 float4s
        int idx = r * MLP_THREADS + t;
        int k = idx >> 4, c = idx & 15;
        ((float4*)Wb)[k * 16 + c] = w1p[k * 64 + c];
    }

    // --- gather atom features (first 32 of 272), store transposed [k][a] ---
    {
        int id = aid[t];   // own-thread write, no sync needed
        float4 row[8];
        if (id >= 0) {
            const float4* ap = (const float4*)(af + (size_t)id * DIN);
            #pragma unroll
            for (int j = 0; j < 8; j++) row[j] = ap[j];
        } else {
            #pragma unroll
            for (int j = 0; j < 8; j++) row[j] = make_float4(0.f, 0.f, 0.f, 0.f);
        }
        #pragma unroll
        for (int j = 0; j < 8; j++) {
            xs[(4 * j + 0) * ATILE + t] = row[j].x;
            xs[(4 * j + 1) * ATILE + t] = row[j].y;
            xs[(4 * j + 2) * ATILE + t] = row[j].z;
            xs[(4 * j + 3) * ATILE + t] = row[j].w;
        }
    }
    __syncthreads();

    const int a0 = (t & 7) * 8;     // atom group
    const int o0 = (t >> 3) * 8;    // output group
    const float RS32 = 0.17677669529663687f;   // 1/sqrt(32)

    // --- stage 1: [64a x 32k x 64o] ---
    {
        float acc[8][8];
        #pragma unroll
        for (int i = 0; i < 8; i++)
            #pragma unroll
            for (int j = 0; j < 8; j++) acc[i][j] = 0.0f;

        #pragma unroll 8
        for (int k = 0; k < IN0; k++) {
            float4 x0 = *(const float4*)&xs[k * ATILE + a0];
            float4 x1 = *(const float4*)&xs[k * ATILE + a0 + 4];
            float4 wA = *(const float4*)&Wa[k * HID + o0];
            float4 wB = *(const float4*)&Wa[k * HID + o0 + 4];
            float xv[8] = {x0.x, x0.y, x0.z, x0.w, x1.x, x1.y, x1.z, x1.w};
            float wv[8] = {wA.x, wA.y, wA.z, wA.w, wB.x, wB.y, wB.z, wB.w};
            #pragma unroll
            for (int i = 0; i < 8; i++)
                #pragma unroll
                for (int j = 0; j < 8; j++)
                    acc[i][j] += xv[i] * wv[j];
        }
        // silu + transposed store: s1 row (o0+j), cols a0..a0+7
        #pragma unroll
        for (int j = 0; j < 8; j++) {
            float4 v0, v1;
            v0.x = silu_f(acc[0][j] * RS32);
            v0.y = silu_f(acc[1][j] * RS32);
            v0.z = silu_f(acc[2][j] * RS32);
            v0.w = silu_f(acc[3][j] * RS32);
            v1.x = silu_f(acc[4][j] * RS32);
            v1.y = silu_f(acc[5][j] * RS32);
            v1.z = silu_f(acc[6][j] * RS32);
            v1.w = silu_f(acc[7][j] * RS32);
            *(float4*)&s1[(o0 + j) * PAD1 + a0]     = v0;
            *(float4*)&s1[(o0 + j) * PAD1 + a0 + 4] = v1;
        }
    }
    __syncthreads();

    // --- stage 2: [64a x 64k x 64o] + silu + REDG scatter into g_acc ---
    {
        float acc[8][8];
        #pragma unroll
        for (int i = 0; i < 8; i++)
            #pragma unroll
            for (int j = 0; j < 8; j++) acc[i][j] = 0.0f;

        #pragma unroll 8
        for (int k = 0; k < HID; k++) {
            float4 x0 = *(const float4*)&s1[k * PAD1 + a0];
            float4 x1 = *(const float4*)&s1[k * PAD1 + a0 + 4];
            float4 wA = *(const float4*)&Wb[k * HID + o0];
            float4 wB = *(const float4*)&Wb[k * HID + o0 + 4];
            float xv[8] = {x0.x, x0.y, x0.z, x0.w, x1.x, x1.y, x1.z, x1.w};
            float wv[8] = {wA.x, wA.y, wA.z, wA.w, wB.x, wB.y, wB.z, wB.w};
            #pragma unroll
            for (int i = 0; i < 8; i++)
                #pragma unroll
                for (int j = 0; j < 8; j++)
                    acc[i][j] += xv[i] * wv[j];
        }

        #pragma unroll
        for (int i = 0; i < 8; i++) {
            int idi = aid[a0 + i];
            if (idi >= 0) {
                int b = idi >> 9;   // / NAT
                float* dst = g_acc + b * (NCLS * HID) + cls * HID + o0;
                #pragma unroll
                for (int j = 0; j < 8; j++)
                    atomicAdd(dst + j, silu_f(acc[i][j] * 0.125f));
            }
        }
    }
}

// ---------------------------------------------------------------------------
// Kernel 3: out[b, cls*128+o] = (g_acc[b][cls][:] @ Wout[cls]) / 8
// Also resets g_cnt for the next invocation (deterministic: g_cnt is zero at
// every kernel_launch entry).
// ---------------------------------------------------------------------------
__global__ __launch_bounds__(NOUT) void out_kernel(
    const float* __restrict__ Wo,   // (T, 64, 128)
    float* __restrict__ out)        // (NB, T*128)
{
    __shared__ float sacc[HID];
    const int cls = blockIdx.x;
    const int b   = blockIdx.y;
    const int t   = threadIdx.x;

    if (t < HID) sacc[t] = g_acc[b * (NCLS * HID) + cls * HID + t];
    if (cls == 0 && b == 0 && t < 16) g_cnt[t] = 0;
    __syncthreads();

    const float* w = Wo + (size_t)cls * HID * NOUT + t;
    float s = 0.0f;
    #pragma unroll
    for (int h = 0; h < HID; h++)
        s += sacc[h] * w[h * NOUT];
    out[b * (NCLS * NOUT) + cls * NOUT + t] = 0.125f * s;
}

// ---------------------------------------------------------------------------
extern "C" void kernel_launch(void* const* d_in, const int* in_sizes, int n_in,
                              void* d_out, int out_size) {
    const float* af      = (const float*)d_in[0];   // atom_features
    const float* W0      = (const float*)d_in[1];   // W0_0
    const float* W1      = (const float*)d_in[5];   // W1_0
    const float* Wo      = (const float*)d_in[9];   // Wout
    const int*   mapping = (const int*)  d_in[10];  // mlp_mapping
    float* out = (float*)d_out;

    prep_compact_kernel<<<NATOMS / 256, 256>>>(mapping);
    mlp_kernel<<<NCLS * TILES_PER_CLASS, MLP_THREADS>>>(af, W0, W1);
    out_kernel<<<dim3(NCLS, NB), NOUT>>>(Wo, out);
}

// round 3
// speedup vs baseline: 1.1951x; 1.1209x over previous
#include <cuda_runtime.h>

#define NCLS   10
#define NB     32
#define NATOMS 16384
#define DIN    272
#define HID    64
#define NOUT   128
#define L0OUT  256
#define IN0    32
#define ATILE  64
#define GRID   296            // 2 blocks/SM on 148 SMs — all co-resident
#define NT     128
#define PADA   68

// static device scratch (module-init zero; lifecycle managed across replays)
__device__ int      g_cnt[16];
__device__ int      g_list[NCLS * NATOMS];
__device__ float    g_acc[NB * NCLS * HID];
__device__ unsigned g_bar0, g_bar1;

__device__ __forceinline__ float silu_f(float x) {
    return x * (1.0f / (1.0f + __expf(-x)));
}

// all-blocks-resident grid barrier (monotonic counter, reset per lifecycle rules)
__device__ __forceinline__ void grid_barrier(unsigned* ctr) {
    __syncthreads();
    if (threadIdx.x == 0) {
        __threadfence();
        atomicAdd(ctr, 1u);
        while (*(volatile unsigned*)ctr < GRID) {}
    }
    __syncthreads();
}

__global__ __launch_bounds__(NT, 2) void fused_kernel(
    const float* __restrict__ af,      // (16384, 272)
    const float* __restrict__ W0,      // (T, 32, 256)
    const float* __restrict__ W1,      // (T, 64, 256)
    const float* __restrict__ Wo,      // (T, 64, 128)
    const int*   __restrict__ mapping, // (16384)
    float*       __restrict__ out)     // (NB, T*128)
{
    __shared__ float Wa[IN0 * HID];     // [k][o]  2048 f
    __shared__ float Wb[HID * HID];     // [k][o]  4096 f
    __shared__ float xs[IN0 * ATILE];   // [k][a]  2048 f (aliased as sacc in ph2)
    __shared__ float s1[HID * PADA];    // [k][a]  4352 f
    __shared__ int   aid[ATILE];

    const int t    = threadIdx.x;
    const int gtid = blockIdx.x * NT + t;

    // ================= phase 0: zero acc + warp-aggregated classify ========
    if (gtid == 0) g_bar1 = 0u;                 // safe: prior launch fully done
    if (gtid < NB * NCLS * HID) g_acc[gtid] = 0.0f;
    if (gtid < NATOMS) {
        int m = mapping[gtid];
        unsigned peers  = __match_any_sync(0xffffffffu, m);
        int lane   = t & 31;
        int leader = __ffs(peers) - 1;
        int rank   = __popc(peers & ((1u << lane) - 1u));
        int base   = 0;
        if (lane == leader) base = atomicAdd(&g_cnt[m], __popc(peers));
        base = __shfl_sync(0xffffffffu, base, leader);
        if (m < NCLS) g_list[m * NATOMS + base + rank] = gtid;
    }
    grid_barrier(&g_bar0);

    // ================= phase 1: per-(class, 64-atom tile) 2-stage MLP ======
    int cls = -1, tb = 0, cnt_c = 0;
    {
        int acc = 0;
        #pragma unroll
        for (int c = 0; c < NCLS; c++) {
            int cc = __ldcg(&g_cnt[c]);
            int nt = (cc + ATILE - 1) >> 6;
            if (cls < 0 && (int)blockIdx.x < acc + nt) {
                cls = c; tb = ((int)blockIdx.x - acc) << 6; cnt_c = cc;
            }
            acc += nt;
        }
    }
    if (cls >= 0) {
        // atom ids + feature gather (transposed [k][a]) — own-thread data
        if (t < ATILE) {
            int i  = tb + t;
            int id = (i < cnt_c) ? __ldcg(&g_list[cls * NATOMS + i]) : -1;
            aid[t] = id;
            float4 row[8];
            if (id >= 0) {
                const float4* ap = (const float4*)(af + (size_t)id * DIN);
                #pragma unroll
                for (int j = 0; j < 8; j++) row[j] = __ldg(&ap[j]);
            } else {
                #pragma unroll
                for (int j = 0; j < 8; j++) row[j] = make_float4(0.f, 0.f, 0.f, 0.f);
            }
            #pragma unroll
            for (int j = 0; j < 8; j++) {
                xs[(4 * j + 0) * ATILE + t] = row[j].x;
                xs[(4 * j + 1) * ATILE + t] = row[j].y;
                xs[(4 * j + 2) * ATILE + t] = row[j].z;
                xs[(4 * j + 3) * ATILE + t] = row[j].w;
            }
        }
        // stage weights (live 64 columns only)
        const float4* w0p = (const float4*)(W0 + (size_t)cls * IN0 * L0OUT);
        #pragma unroll
        for (int r = 0; r < 4; r++) {
            int idx = r * NT + t, k = idx >> 4, c = idx & 15;
            ((float4*)Wa)[k * 16 + c] = __ldg(&w0p[k * 64 + c]);
        }
        const float4* w1p = (const float4*)(W1 + (size_t)cls * HID * L0OUT);
        #pragma unroll
        for (int r = 0; r < 8; r++) {
            int idx = r * NT + t, k = idx >> 4, c = idx & 15;
            ((float4*)Wb)[k * 16 + c] = __ldg(&w1p[k * 64 + c]);
        }
        __syncthreads();

        const int a0 = (t & 15) << 2;   // 4-atom group
        const int o0 = (t >> 4) << 3;   // 8-output group
        const float RS32 = 0.17677669529663687f;

        // ---- stage 1: [64a x 32k x 64o] ----
        float acc1[4][8];
        #pragma unroll
        for (int i = 0; i < 4; i++)
            #pragma unroll
            for (int j = 0; j < 8; j++) acc1[i][j] = 0.0f;
        #pragma unroll
        for (int k = 0; k < IN0; k++) {
            float4 x4 = *(const float4*)&xs[k * ATILE + a0];
            float4 wA = *(const float4*)&Wa[k * HID + o0];
            float4 wB = *(const float4*)&Wa[k * HID + o0 + 4];
            float xv[4] = {x4.x, x4.y, x4.z, x4.w};
            float wv[8] = {wA.x, wA.y, wA.z, wA.w, wB.x, wB.y, wB.z, wB.w};
            #pragma unroll
            for (int i = 0; i < 4; i++)
                #pragma unroll
                for (int j = 0; j < 8; j++) acc1[i][j] += xv[i] * wv[j];
        }
        #pragma unroll
        for (int j = 0; j < 8; j++) {       // silu + transpose to [o][a]
            float4 v;
            v.x = silu_f(acc1[0][j] * RS32);
            v.y = silu_f(acc1[1][j] * RS32);
            v.z = silu_f(acc1[2][j] * RS32);
            v.w = silu_f(acc1[3][j] * RS32);
            *(float4*)&s1[(o0 + j) * PADA + a0] = v;
        }
        __syncthreads();

        // ---- stage 2: [64a x 64k x 64o] + silu + scatter-add ----
        float acc2[4][8];
        #pragma unroll
        for (int i = 0; i < 4; i++)
            #pragma unroll
            for (int j = 0; j < 8; j++) acc2[i][j] = 0.0f;
        #pragma unroll
        for (int k = 0; k < HID; k++) {
            float4 x4 = *(const float4*)&s1[k * PADA + a0];
            float4 wA = *(const float4*)&Wb[k * HID + o0];
            float4 wB = *(const float4*)&Wb[k * HID + o0 + 4];
            float xv[4] = {x4.x, x4.y, x4.z, x4.w};
            float wv[8] = {wA.x, wA.y, wA.z, wA.w, wB.x, wB.y, wB.z, wB.w};
            #pragma unroll
            for (int i = 0; i < 4; i++)
                #pragma unroll
                for (int j = 0; j < 8; j++) acc2[i][j] += xv[i] * wv[j];
        }
        #pragma unroll
        for (int i = 0; i < 4; i++) {
            int id = aid[a0 + i];
            if (id >= 0) {
                int b = id >> 9;            // / NAT
                float* dst = &g_acc[b * (NCLS * HID) + cls * HID + o0];
                #pragma unroll
                for (int j = 0; j < 8; j++)
                    atomicAdd(dst + j, silu_f(acc2[i][j] * 0.125f));
            }
        }
    }
    grid_barrier(&g_bar1);

    // ================= phase 2: out = (sum s2) @ Wout / 8 + lifecycle reset =
    if (blockIdx.x == 0 && t == 0) {
        g_bar0 = 0u;                        // all blocks past barrier 0
        #pragma unroll
        for (int i = 0; i < 16; i++) g_cnt[i] = 0;
    }
    float* sacc = xs;                       // reuse (phase 1 done at barrier 1)
    for (int w = blockIdx.x; w < NB * NCLS; w += GRID) {
        int c2 = w >> 5;                    // class
        int b  = w & 31;                    // batch
        __syncthreads();
        if (t < HID) sacc[t] = __ldcg(&g_acc[b * (NCLS * HID) + c2 * HID + t]);
        __syncthreads();
        const float* wp = Wo + (size_t)c2 * HID * NOUT + t;
        float s = 0.0f;
        #pragma unroll
        for (int h = 0; h < HID; h++) s += sacc[h] * __ldg(&wp[h * NOUT]);
        out[b * (NCLS * NOUT) + c2 * NOUT + t] = 0.125f * s;
    }
}

// ---------------------------------------------------------------------------
extern "C" void kernel_launch(void* const* d_in, const int* in_sizes, int n_in,
                              void* d_out, int out_size) {
    const float* af      = (const float*)d_in[0];   // atom_features
    const float* W0      = (const float*)d_in[1];   // W0_0
    const float* W1      = (const float*)d_in[5];   // W1_0
    const float* Wo      = (const float*)d_in[9];   // Wout
    const int*   mapping = (const int*)  d_in[10];  // mlp_mapping
    float* out = (float*)d_out;

    fused_kernel<<<GRID, NT>>>(af, W0, W1, Wo, mapping, out);
}